// round 3
// baseline (speedup 1.0000x reference)
#include <cuda_runtime.h>
#include <math.h>

#define NNODES 100000
#define NEDGES 1600000
#define ETOT   (NEDGES + NNODES)
#define F      128
#define NG     128
#define NC     10
#define SCAN_B 1024
#define NSB    ((NNODES + SCAN_B - 1) / SCAN_B)

// ---------------- scratch (device globals; no allocation allowed) -------------
__device__ __align__(256) int   g_deg[NNODES];
__device__ __align__(256) int   g_off[NNODES + 1];
__device__ __align__(256) int   g_cur[NNODES];
__device__ __align__(256) float g_dis[NNODES];
__device__ __align__(256) int   g_ccol[ETOT];
__device__ __align__(256) float g_cnrm[ETOT];
__device__ __align__(256) float g_h[(size_t)NNODES * F];   // GEMM output
__device__ __align__(256) float g_x[(size_t)NNODES * F];   // aggregated/relu output
__device__ __align__(256) float g_pool[NG * 2 * F];
__device__ int g_bs[NSB];
__device__ int g_flags[2];   // [0]: EI is int64, [1]: batch is int64

// ---------------- helpers ----------------------------------------------------
__device__ __forceinline__ int load_idx(const void* p, long long i, int is64) {
    return is64 ? (int)(((const long long*)p)[i]) : ((const int*)p)[i];
}

// Detect whether index arrays are int64 or int32 (jax x64 ambiguity).
// batch: the int32 view of a sorted int64 array (values < 128) looks like
// v,0,v,0,... which breaks monotonicity at the first v>=1. So: batch is int32
// iff its int32 view is non-decreasing and in-range over the whole array.
// EI: int64 iff sampled int64 reads are in [0, NNODES) — random int32 pairs
// interpreted as int64 are astronomically out of range.
__global__ void k_detect(const void* ei, const void* batch) {
    __shared__ int s_bad;
    if (threadIdx.x == 0) s_bad = 0;
    __syncthreads();
    const int* b32 = (const int*)batch;
    int bad = 0;
    for (int j = threadIdx.x; j < NNODES - 1; j += blockDim.x) {
        int a = b32[j], c = b32[j + 1];
        if (a < 0 || a >= NG || c < a) { bad = 1; break; }
    }
    if (bad) atomicExch(&s_bad, 1);
    __syncthreads();
    if (threadIdx.x == 0) {
        g_flags[1] = s_bad ? 1 : 0;   // non-monotone int32 view -> int64
        const long long* p = (const long long*)ei;
        int ok = 1;
        for (int i = 0; i < 64; i++) {
            long long v = p[(long long)i * 317 + 1];
            if (v < 0 || v >= NNODES) { ok = 0; break; }
        }
        g_flags[0] = ok;
    }
}

__global__ void k_init_deg() {
    int i = blockIdx.x * blockDim.x + threadIdx.x;
    if (i < NNODES) g_deg[i] = 1;   // self-loop
}

__global__ void k_hist(const void* ei) {
    int is64 = g_flags[0];
    int i = blockIdx.x * blockDim.x + threadIdx.x;
    if (i < NEDGES) {
        int r = load_idx(ei, i, is64);
        atomicAdd(&g_deg[r], 1);
    }
}

__global__ void k_scan1() {
    __shared__ int s[SCAN_B];
    int i = blockIdx.x * SCAN_B + threadIdx.x;
    int v = (i < NNODES) ? g_deg[i] : 0;
    s[threadIdx.x] = v;
    __syncthreads();
    for (int d = SCAN_B / 2; d > 0; d >>= 1) {
        if (threadIdx.x < d) s[threadIdx.x] += s[threadIdx.x + d];
        __syncthreads();
    }
    if (threadIdx.x == 0) g_bs[blockIdx.x] = s[0];
}

__global__ void k_scan2() {
    if (threadIdx.x == 0 && blockIdx.x == 0) {
        int run = 0;
        for (int b = 0; b < NSB; b++) { int t = g_bs[b]; g_bs[b] = run; run += t; }
        g_off[NNODES] = run;  // == ETOT
    }
}

__global__ void k_scan3() {
    __shared__ int s[SCAN_B];
    int tid = threadIdx.x;
    int i = blockIdx.x * SCAN_B + tid;
    int v = (i < NNODES) ? g_deg[i] : 0;
    s[tid] = v;
    __syncthreads();
    // inclusive Hillis-Steele
    for (int d = 1; d < SCAN_B; d <<= 1) {
        int t = (tid >= d) ? s[tid - d] : 0;
        __syncthreads();
        s[tid] += t;
        __syncthreads();
    }
    if (i < NNODES) {
        int excl = s[tid] - v + g_bs[blockIdx.x];
        g_off[i] = excl;
        g_cur[i] = excl;
        g_dis[i] = rsqrtf((float)v + 1e-12f);
    }
}

__global__ void k_fill(const void* ei) {
    int is64 = g_flags[0];
    int i = blockIdx.x * blockDim.x + threadIdx.x;
    if (i < NEDGES) {
        int r = load_idx(ei, i, is64);
        int c = load_idx(ei, (long long)NEDGES + i, is64);
        int p = atomicAdd(&g_cur[r], 1);
        g_ccol[p] = c;
        g_cnrm[p] = g_dis[r] * g_dis[c];
    } else if (i < ETOT) {
        int nidx = i - NEDGES;
        int p = atomicAdd(&g_cur[nidx], 1);
        g_ccol[p] = nidx;
        float d = g_dis[nidx];
        g_cnrm[p] = d * d;
    }
}

// ---------------- GEMM: out[n,:] = in[n,:] @ W + b  (128x128 W in smem) ------
// Block: 256 threads = 8 warps; each warp computes 4 nodes; block does 32 nodes.
__global__ void k_gemm(const float* __restrict__ in, const float* __restrict__ W,
                       const float* __restrict__ b, float* __restrict__ out) {
    extern __shared__ float sm[];
    float* Ws = sm;               // 128*128
    float* xs = sm + F * F;       // 32*128
    __shared__ float bs_[F];

    const float4* W4 = (const float4*)W;
    float4* Ws4 = (float4*)Ws;
    for (int i = threadIdx.x; i < F * F / 4; i += blockDim.x) Ws4[i] = W4[i];
    for (int i = threadIdx.x; i < F; i += blockDim.x) bs_[i] = b[i];

    int node0 = blockIdx.x * 32;
    float4* xs4 = (float4*)xs;
    const float4* in4 = (const float4*)in;
    for (int i = threadIdx.x; i < 32 * (F / 4); i += blockDim.x) {
        int node = node0 + i / (F / 4);
        xs4[i] = (node < NNODES) ? in4[(size_t)node * (F / 4) + (i & (F / 4 - 1))]
                                 : make_float4(0.f, 0.f, 0.f, 0.f);
    }
    __syncthreads();

    int warp = threadIdx.x >> 5, lane = threadIdx.x & 31;
    int nl0 = warp * 4;
    float4 bv = ((float4*)bs_)[lane];
    float4 acc[4];
#pragma unroll
    for (int u = 0; u < 4; u++) acc[u] = bv;

#pragma unroll 4
    for (int j = 0; j < 32; j++) {
        float4 w0 = ((float4*)Ws)[(4 * j + 0) * 32 + lane];
        float4 w1 = ((float4*)Ws)[(4 * j + 1) * 32 + lane];
        float4 w2 = ((float4*)Ws)[(4 * j + 2) * 32 + lane];
        float4 w3 = ((float4*)Ws)[(4 * j + 3) * 32 + lane];
#pragma unroll
        for (int u = 0; u < 4; u++) {
            float4 xv = ((float4*)xs)[(nl0 + u) * 32 + j];
            acc[u].x = fmaf(xv.x, w0.x, fmaf(xv.y, w1.x, fmaf(xv.z, w2.x, fmaf(xv.w, w3.x, acc[u].x))));
            acc[u].y = fmaf(xv.x, w0.y, fmaf(xv.y, w1.y, fmaf(xv.z, w2.y, fmaf(xv.w, w3.y, acc[u].y))));
            acc[u].z = fmaf(xv.x, w0.z, fmaf(xv.y, w1.z, fmaf(xv.z, w2.z, fmaf(xv.w, w3.z, acc[u].z))));
            acc[u].w = fmaf(xv.x, w0.w, fmaf(xv.y, w1.w, fmaf(xv.z, w2.w, fmaf(xv.w, w3.w, acc[u].w))));
        }
    }
#pragma unroll
    for (int u = 0; u < 4; u++) {
        int node = node0 + nl0 + u;
        if (node < NNODES) ((float4*)out)[(size_t)node * 32 + lane] = acc[u];
    }
}

// ---------------- aggregation: warp per node; gather h[col]*norm, relu -------
__global__ void k_agg(const float* __restrict__ h, float* __restrict__ xo) {
    int gw = (blockIdx.x * blockDim.x + threadIdx.x) >> 5;
    int lane = threadIdx.x & 31;
    if (gw >= NNODES) return;
    int beg = g_off[gw], end = g_off[gw + 1];
    const float4* h4 = (const float4*)h;
    float4 acc = make_float4(0.f, 0.f, 0.f, 0.f);
    for (int e = beg; e < end; e++) {
        int c = g_ccol[e];
        float nrm = g_cnrm[e];
        float4 v = h4[(size_t)c * 32 + lane];
        acc.x = fmaf(nrm, v.x, acc.x);
        acc.y = fmaf(nrm, v.y, acc.y);
        acc.z = fmaf(nrm, v.z, acc.z);
        acc.w = fmaf(nrm, v.w, acc.w);
    }
    acc.x = fmaxf(acc.x, 0.f);
    acc.y = fmaxf(acc.y, 0.f);
    acc.z = fmaxf(acc.z, 0.f);
    acc.w = fmaxf(acc.w, 0.f);
    ((float4*)xo)[(size_t)gw * 32 + lane] = acc;
}

// ---------------- pooling: block per graph, batch is sorted ------------------
__device__ __forceinline__ int lbound(const void* b, int is64, long long key) {
    int lo = 0, hi = NNODES;
    while (lo < hi) {
        int mid = (lo + hi) >> 1;
        long long v = is64 ? ((const long long*)b)[mid] : (long long)((const int*)b)[mid];
        if (v < key) lo = mid + 1; else hi = mid;
    }
    return lo;
}

__global__ void k_pool(const void* batch) {
    int g = blockIdx.x, tid = threadIdx.x;
    int is64 = g_flags[1];
    int s = lbound(batch, is64, g);
    int e = lbound(batch, is64, g + 1);
    float sum = 0.f, mx = -3.4e38f;
    for (int n = s; n < e; n++) {
        float v = g_x[(size_t)n * F + tid];
        sum += v;
        mx = fmaxf(mx, v);
    }
    int cnt = e - s;
    float mean = sum / ((float)cnt + 1e-12f);
    if (cnt == 0) mx = 0.f;
    g_pool[g * 2 * F + tid] = mean;
    g_pool[g * 2 * F + F + tid] = mx;
}

// ---------------- MLP head: block per graph ----------------------------------
__global__ void k_mlp(const float* __restrict__ Wm1, const float* __restrict__ bm1,
                      const float* __restrict__ Wm2, const float* __restrict__ bm2,
                      float* __restrict__ out) {
    __shared__ float gs[2 * F];
    __shared__ float hs[F];
    int g = blockIdx.x, tid = threadIdx.x;
    gs[tid] = g_pool[g * 2 * F + tid];
    gs[F + tid] = g_pool[g * 2 * F + F + tid];
    __syncthreads();
    float acc = bm1[tid];
#pragma unroll 8
    for (int k = 0; k < 2 * F; k++) acc = fmaf(gs[k], Wm1[k * F + tid], acc);
    hs[tid] = fmaxf(acc, 0.f);
    __syncthreads();
    if (tid < NC) {
        float a = bm2[tid];
#pragma unroll 8
        for (int k = 0; k < F; k++) a = fmaf(hs[k], Wm2[k * NC + tid], a);
        out[g * NC + tid] = a;
    }
}

// ---------------- launch ------------------------------------------------------
extern "C" void kernel_launch(void* const* d_in, const int* in_sizes, int n_in,
                              void* d_out, int out_size) {
    // Locate inputs by element count (robust to presence/absence of num_graphs scalar).
    int iX = -1, iEI = -1, iB = -1, iW[3] = {-1, -1, -1}, ibv[4] = {-1, -1, -1, -1};
    int nw = 0, nb = 0, iWm1 = -1, iWm2 = -1, ibm2 = -1;
    for (int i = 0; i < n_in; i++) {
        int s = in_sizes[i];
        if (s == NNODES * F) iX = i;
        else if (s == 2 * NEDGES) iEI = i;
        else if (s == NNODES) iB = i;
        else if (s == F * F) { if (nw < 3) iW[nw++] = i; }
        else if (s == F) { if (nb < 4) ibv[nb++] = i; }
        else if (s == 2 * F * F) iWm1 = i;
        else if (s == F * NC) iWm2 = i;
        else if (s == NC) ibm2 = i;
    }
    const float* X   = (const float*)d_in[iX];
    const void*  EI  = d_in[iEI];
    const void*  BT  = d_in[iB];
    const float* W1  = (const float*)d_in[iW[0]];
    const float* W2  = (const float*)d_in[iW[1]];
    const float* W3  = (const float*)d_in[iW[2]];
    const float* b1  = (const float*)d_in[ibv[0]];
    const float* b2  = (const float*)d_in[ibv[1]];
    const float* b3  = (const float*)d_in[ibv[2]];
    const float* bm1 = (const float*)d_in[ibv[3]];
    const float* Wm1 = (const float*)d_in[iWm1];
    const float* Wm2 = (const float*)d_in[iWm2];
    const float* bm2 = (const float*)d_in[ibm2];
    float* out = (float*)d_out;

    void *ph = nullptr, *px = nullptr;
    cudaGetSymbolAddress(&ph, g_h);
    cudaGetSymbolAddress(&px, g_x);
    float* H = (float*)ph;
    float* Xb = (float*)px;

    size_t shm = (size_t)(F * F + 32 * F) * sizeof(float);
    cudaFuncSetAttribute(k_gemm, cudaFuncAttributeMaxDynamicSharedMemorySize, (int)shm);

    // graph preprocessing (runs every replay)
    k_detect<<<1, 256>>>(EI, BT);
    k_init_deg<<<(NNODES + 255) / 256, 256>>>();
    k_hist<<<(NEDGES + 255) / 256, 256>>>(EI);
    k_scan1<<<NSB, SCAN_B>>>();
    k_scan2<<<1, 32>>>();
    k_scan3<<<NSB, SCAN_B>>>();
    k_fill<<<(ETOT + 255) / 256, 256>>>(EI);

    int gemm_grid = (NNODES + 31) / 32;
    int agg_grid = (NNODES * 32 + 255) / 256;

    // layer 1
    k_gemm<<<gemm_grid, 256, shm>>>(X, W1, b1, H);
    k_agg<<<agg_grid, 256>>>(H, Xb);
    // layer 2
    k_gemm<<<gemm_grid, 256, shm>>>(Xb, W2, b2, H);
    k_agg<<<agg_grid, 256>>>(H, Xb);
    // layer 3
    k_gemm<<<gemm_grid, 256, shm>>>(Xb, W3, b3, H);
    k_agg<<<agg_grid, 256>>>(H, Xb);

    // pool + head
    k_pool<<<NG, F>>>(BT);
    k_mlp<<<NG, F>>>(Wm1, bm1, Wm2, bm2, out);
}

// round 4
// speedup vs baseline: 1.2293x; 1.2293x over previous
#include <cuda_runtime.h>
#include <math.h>

#define NNODES 100000
#define NEDGES 1600000
#define ETOT   (NEDGES + NNODES)
#define F      128
#define NG     128
#define NC     10
#define SCAN_B 1024
#define NSB    ((NNODES + SCAN_B - 1) / SCAN_B)
#define NB     64      // nodes per GEMM block
#define XPAD   66      // transposed-x row pad (8B alignment + reduced conflicts)

// ---------------- scratch (device globals; no allocation allowed) -------------
__device__ __align__(256) int   g_deg[NNODES];
__device__ __align__(256) int   g_off[NNODES + 1];
__device__ __align__(256) int   g_cur[NNODES];
__device__ __align__(256) float g_dis[NNODES];
__device__ __align__(256) int   g_ccol[ETOT];
__device__ __align__(256) float g_cnrm[ETOT];
__device__ __align__(256) float g_h[(size_t)NNODES * F];
__device__ __align__(256) float g_x[(size_t)NNODES * F];
__device__ __align__(256) float g_pool[NG * 2 * F];
__device__ int g_bs[NSB];
__device__ int g_flags[2];

// ---------------- f32x2 helpers (Blackwell packed fp32: 2x FFMA rate) --------
__device__ __forceinline__ unsigned long long pack2(float x) {
    unsigned long long r;
    asm("mov.b64 %0, {%1, %1};" : "=l"(r) : "f"(x));
    return r;
}
__device__ __forceinline__ void ffma2(unsigned long long& d, unsigned long long a,
                                      unsigned long long b) {
    asm("fma.rn.f32x2 %0, %1, %2, %0;" : "+l"(d) : "l"(a), "l"(b));
}
__device__ __forceinline__ float lo32(unsigned long long v) { return __uint_as_float((unsigned)v); }
__device__ __forceinline__ float hi32(unsigned long long v) { return __uint_as_float((unsigned)(v >> 32)); }

// ---------------- helpers ----------------------------------------------------
__device__ __forceinline__ int load_idx(const void* p, long long i, int is64) {
    return is64 ? (int)(((const long long*)p)[i]) : ((const int*)p)[i];
}

// dtype detection (jax x64 ambiguity); see round-1 notes.
__global__ void k_detect(const void* ei, const void* batch) {
    __shared__ int s_bad;
    if (threadIdx.x == 0) s_bad = 0;
    __syncthreads();
    const int* b32 = (const int*)batch;
    int bad = 0;
    for (int j = threadIdx.x; j < NNODES - 1; j += blockDim.x) {
        int a = b32[j], c = b32[j + 1];
        if (a < 0 || a >= NG || c < a) { bad = 1; break; }
    }
    if (bad) atomicExch(&s_bad, 1);
    __syncthreads();
    if (threadIdx.x == 0) {
        g_flags[1] = s_bad ? 1 : 0;
        const long long* p = (const long long*)ei;
        int ok = 1;
        for (int i = 0; i < 64; i++) {
            long long v = p[(long long)i * 317 + 1];
            if (v < 0 || v >= NNODES) { ok = 0; break; }
        }
        g_flags[0] = ok;
    }
}

__global__ void k_init_deg() {
    int i = blockIdx.x * blockDim.x + threadIdx.x;
    if (i < NNODES) g_deg[i] = 1;
}

__global__ void k_hist(const void* ei) {
    int is64 = g_flags[0];
    int i = blockIdx.x * blockDim.x + threadIdx.x;
    if (i < NEDGES) {
        int r = load_idx(ei, i, is64);
        atomicAdd(&g_deg[r], 1);
    }
}

__global__ void k_scan1() {
    __shared__ int s[SCAN_B];
    int i = blockIdx.x * SCAN_B + threadIdx.x;
    int v = (i < NNODES) ? g_deg[i] : 0;
    s[threadIdx.x] = v;
    __syncthreads();
    for (int d = SCAN_B / 2; d > 0; d >>= 1) {
        if (threadIdx.x < d) s[threadIdx.x] += s[threadIdx.x + d];
        __syncthreads();
    }
    if (threadIdx.x == 0) g_bs[blockIdx.x] = s[0];
}

__global__ void k_scan2() {
    if (threadIdx.x == 0 && blockIdx.x == 0) {
        int run = 0;
        for (int b = 0; b < NSB; b++) { int t = g_bs[b]; g_bs[b] = run; run += t; }
        g_off[NNODES] = run;
    }
}

__global__ void k_scan3() {
    __shared__ int s[SCAN_B];
    int tid = threadIdx.x;
    int i = blockIdx.x * SCAN_B + tid;
    int v = (i < NNODES) ? g_deg[i] : 0;
    s[tid] = v;
    __syncthreads();
    for (int d = 1; d < SCAN_B; d <<= 1) {
        int t = (tid >= d) ? s[tid - d] : 0;
        __syncthreads();
        s[tid] += t;
        __syncthreads();
    }
    if (i < NNODES) {
        int excl = s[tid] - v + g_bs[blockIdx.x];
        g_off[i] = excl;
        g_cur[i] = excl;
        g_dis[i] = rsqrtf((float)v + 1e-12f);
    }
}

__global__ void k_fill(const void* ei) {
    int is64 = g_flags[0];
    int i = blockIdx.x * blockDim.x + threadIdx.x;
    if (i < NEDGES) {
        int r = load_idx(ei, i, is64);
        int c = load_idx(ei, (long long)NEDGES + i, is64);
        int p = atomicAdd(&g_cur[r], 1);
        g_ccol[p] = c;
        g_cnrm[p] = g_dis[r] * g_dis[c];
    } else if (i < ETOT) {
        int nidx = i - NEDGES;
        int p = atomicAdd(&g_cur[nidx], 1);
        g_ccol[p] = nidx;
        float d = g_dis[nidx];
        g_cnrm[p] = d * d;
    }
}

// ---------------- GEMM with packed f32x2 FFMA --------------------------------
// Block: 256 threads = 8 warps; 64 nodes/block, 8 nodes/warp as 4 node-PAIRS.
// Each FFMA2 computes (acc[n0][c], acc[n1][c]) += (x[n0][k], x[n1][k]) * (w,w).
// a-operand: natural u64 from transposed x tile; b-operand: w duplicated once
// per j-iter, reused across 4 pairs. Lane owns cols 4*lane..4*lane+3.
__global__ __launch_bounds__(256, 2)
void k_gemm(const float* __restrict__ in, const float* __restrict__ W,
            const float* __restrict__ b, float* __restrict__ out) {
    extern __shared__ float sm[];
    float* Ws = sm;                 // 128 x 128
    float* xs = sm + F * F;         // 128 x XPAD (transposed: xs[k*XPAD + n])

    const float4* W4 = (const float4*)W;
    float4* Ws4 = (float4*)Ws;
    for (int i = threadIdx.x; i < F * F / 4; i += 256) Ws4[i] = W4[i];

    int node0 = blockIdx.x * NB;
    const float4* in4 = (const float4*)in;
    for (int i = threadIdx.x; i < NB * 32; i += 256) {
        int n = i >> 5, kg = i & 31;       // lanes: consecutive kg, same n -> coalesced read
        int node = node0 + n;
        float4 v = (node < NNODES) ? in4[(size_t)node * 32 + kg]
                                   : make_float4(0.f, 0.f, 0.f, 0.f);
        xs[(4 * kg + 0) * XPAD + n] = v.x;
        xs[(4 * kg + 1) * XPAD + n] = v.y;
        xs[(4 * kg + 2) * XPAD + n] = v.z;
        xs[(4 * kg + 3) * XPAD + n] = v.w;
    }
    __syncthreads();

    int warp = threadIdx.x >> 5, lane = threadIdx.x & 31;
    int nb = warp * 8;   // node base (within block) for this warp

    unsigned long long bb[4];
#pragma unroll
    for (int d = 0; d < 4; d++) bb[d] = pack2(b[4 * lane + d]);

    unsigned long long acc[4][4];   // [pair][d]
#pragma unroll
    for (int p = 0; p < 4; p++)
#pragma unroll
        for (int d = 0; d < 4; d++) acc[p][d] = bb[d];

#pragma unroll 4
    for (int j = 0; j < 32; j++) {
        float4 w0 = Ws4[(4 * j + 0) * 32 + lane];
        float4 w1 = Ws4[(4 * j + 1) * 32 + lane];
        float4 w2 = Ws4[(4 * j + 2) * 32 + lane];
        float4 w3 = Ws4[(4 * j + 3) * 32 + lane];
        unsigned long long wd[4][4];
        wd[0][0] = pack2(w0.x); wd[0][1] = pack2(w0.y); wd[0][2] = pack2(w0.z); wd[0][3] = pack2(w0.w);
        wd[1][0] = pack2(w1.x); wd[1][1] = pack2(w1.y); wd[1][2] = pack2(w1.z); wd[1][3] = pack2(w1.w);
        wd[2][0] = pack2(w2.x); wd[2][1] = pack2(w2.y); wd[2][2] = pack2(w2.z); wd[2][3] = pack2(w2.w);
        wd[3][0] = pack2(w3.x); wd[3][1] = pack2(w3.y); wd[3][2] = pack2(w3.z); wd[3][3] = pack2(w3.w);
#pragma unroll
        for (int p = 0; p < 4; p++) {
            int nidx = nb + 2 * p;   // even; XPAD even -> 8B-aligned u64 loads
#pragma unroll
            for (int kk = 0; kk < 4; kk++) {
                unsigned long long a =
                    *(const unsigned long long*)&xs[(4 * j + kk) * XPAD + nidx];
                ffma2(acc[p][0], a, wd[kk][0]);
                ffma2(acc[p][1], a, wd[kk][1]);
                ffma2(acc[p][2], a, wd[kk][2]);
                ffma2(acc[p][3], a, wd[kk][3]);
            }
        }
    }

    float4* out4 = (float4*)out;
#pragma unroll
    for (int p = 0; p < 4; p++) {
        int n0 = node0 + nb + 2 * p;
        int n1 = n0 + 1;
        float4 lo = make_float4(lo32(acc[p][0]), lo32(acc[p][1]), lo32(acc[p][2]), lo32(acc[p][3]));
        float4 hi = make_float4(hi32(acc[p][0]), hi32(acc[p][1]), hi32(acc[p][2]), hi32(acc[p][3]));
        if (n0 < NNODES) out4[(size_t)n0 * 32 + lane] = lo;
        if (n1 < NNODES) out4[(size_t)n1 * 32 + lane] = hi;
    }
}

// ---------------- aggregation: warp per node; 4x unrolled gather -------------
__global__ void k_agg(const float* __restrict__ h, float* __restrict__ xo) {
    int gw = (blockIdx.x * blockDim.x + threadIdx.x) >> 5;
    int lane = threadIdx.x & 31;
    if (gw >= NNODES) return;
    int beg = g_off[gw], end = g_off[gw + 1];
    const float4* h4 = (const float4*)h;
    float4 acc = make_float4(0.f, 0.f, 0.f, 0.f);
    int e = beg;
    for (; e + 4 <= end; e += 4) {
        int c0 = g_ccol[e], c1 = g_ccol[e + 1], c2 = g_ccol[e + 2], c3 = g_ccol[e + 3];
        float m0 = g_cnrm[e], m1 = g_cnrm[e + 1], m2 = g_cnrm[e + 2], m3 = g_cnrm[e + 3];
        float4 v0 = h4[(size_t)c0 * 32 + lane];
        float4 v1 = h4[(size_t)c1 * 32 + lane];
        float4 v2 = h4[(size_t)c2 * 32 + lane];
        float4 v3 = h4[(size_t)c3 * 32 + lane];
        acc.x = fmaf(m0, v0.x, fmaf(m1, v1.x, fmaf(m2, v2.x, fmaf(m3, v3.x, acc.x))));
        acc.y = fmaf(m0, v0.y, fmaf(m1, v1.y, fmaf(m2, v2.y, fmaf(m3, v3.y, acc.y))));
        acc.z = fmaf(m0, v0.z, fmaf(m1, v1.z, fmaf(m2, v2.z, fmaf(m3, v3.z, acc.z))));
        acc.w = fmaf(m0, v0.w, fmaf(m1, v1.w, fmaf(m2, v2.w, fmaf(m3, v3.w, acc.w))));
    }
    for (; e < end; e++) {
        int c = g_ccol[e];
        float nrm = g_cnrm[e];
        float4 v = h4[(size_t)c * 32 + lane];
        acc.x = fmaf(nrm, v.x, acc.x);
        acc.y = fmaf(nrm, v.y, acc.y);
        acc.z = fmaf(nrm, v.z, acc.z);
        acc.w = fmaf(nrm, v.w, acc.w);
    }
    acc.x = fmaxf(acc.x, 0.f);
    acc.y = fmaxf(acc.y, 0.f);
    acc.z = fmaxf(acc.z, 0.f);
    acc.w = fmaxf(acc.w, 0.f);
    ((float4*)xo)[(size_t)gw * 32 + lane] = acc;
}

// ---------------- pooling ----------------------------------------------------
__device__ __forceinline__ int lbound(const void* b, int is64, long long key) {
    int lo = 0, hi = NNODES;
    while (lo < hi) {
        int mid = (lo + hi) >> 1;
        long long v = is64 ? ((const long long*)b)[mid] : (long long)((const int*)b)[mid];
        if (v < key) lo = mid + 1; else hi = mid;
    }
    return lo;
}

__global__ void k_pool(const void* batch) {
    int g = blockIdx.x, tid = threadIdx.x;
    int is64 = g_flags[1];
    int s = lbound(batch, is64, g);
    int e = lbound(batch, is64, g + 1);
    float sum = 0.f, mx = -3.4e38f;
    int n = s;
    for (; n + 2 <= e; n += 2) {
        float v0 = g_x[(size_t)n * F + tid];
        float v1 = g_x[(size_t)(n + 1) * F + tid];
        sum += v0 + v1;
        mx = fmaxf(mx, fmaxf(v0, v1));
    }
    for (; n < e; n++) {
        float v = g_x[(size_t)n * F + tid];
        sum += v;
        mx = fmaxf(mx, v);
    }
    int cnt = e - s;
    float mean = sum / ((float)cnt + 1e-12f);
    if (cnt == 0) mx = 0.f;
    g_pool[g * 2 * F + tid] = mean;
    g_pool[g * 2 * F + F + tid] = mx;
}

// ---------------- MLP head ----------------------------------------------------
__global__ void k_mlp(const float* __restrict__ Wm1, const float* __restrict__ bm1,
                      const float* __restrict__ Wm2, const float* __restrict__ bm2,
                      float* __restrict__ out) {
    __shared__ float gs[2 * F];
    __shared__ float hs[F];
    int g = blockIdx.x, tid = threadIdx.x;
    gs[tid] = g_pool[g * 2 * F + tid];
    gs[F + tid] = g_pool[g * 2 * F + F + tid];
    __syncthreads();
    float acc = bm1[tid];
#pragma unroll 8
    for (int k = 0; k < 2 * F; k++) acc = fmaf(gs[k], Wm1[k * F + tid], acc);
    hs[tid] = fmaxf(acc, 0.f);
    __syncthreads();
    if (tid < NC) {
        float a = bm2[tid];
#pragma unroll 8
        for (int k = 0; k < F; k++) a = fmaf(hs[k], Wm2[k * NC + tid], a);
        out[g * NC + tid] = a;
    }
}

// ---------------- launch ------------------------------------------------------
extern "C" void kernel_launch(void* const* d_in, const int* in_sizes, int n_in,
                              void* d_out, int out_size) {
    int iX = -1, iEI = -1, iB = -1, iW[3] = {-1, -1, -1}, ibv[4] = {-1, -1, -1, -1};
    int nw = 0, nb = 0, iWm1 = -1, iWm2 = -1, ibm2 = -1;
    for (int i = 0; i < n_in; i++) {
        int s = in_sizes[i];
        if (s == NNODES * F) iX = i;
        else if (s == 2 * NEDGES) iEI = i;
        else if (s == NNODES) iB = i;
        else if (s == F * F) { if (nw < 3) iW[nw++] = i; }
        else if (s == F) { if (nb < 4) ibv[nb++] = i; }
        else if (s == 2 * F * F) iWm1 = i;
        else if (s == F * NC) iWm2 = i;
        else if (s == NC) ibm2 = i;
    }
    const float* X   = (const float*)d_in[iX];
    const void*  EI  = d_in[iEI];
    const void*  BT  = d_in[iB];
    const float* W1  = (const float*)d_in[iW[0]];
    const float* W2  = (const float*)d_in[iW[1]];
    const float* W3  = (const float*)d_in[iW[2]];
    const float* b1  = (const float*)d_in[ibv[0]];
    const float* b2  = (const float*)d_in[ibv[1]];
    const float* b3  = (const float*)d_in[ibv[2]];
    const float* bm1 = (const float*)d_in[ibv[3]];
    const float* Wm1 = (const float*)d_in[iWm1];
    const float* Wm2 = (const float*)d_in[iWm2];
    const float* bm2 = (const float*)d_in[ibm2];
    float* out = (float*)d_out;

    void *ph = nullptr, *px = nullptr;
    cudaGetSymbolAddress(&ph, g_h);
    cudaGetSymbolAddress(&px, g_x);
    float* H = (float*)ph;
    float* Xb = (float*)px;

    size_t shm = (size_t)(F * F + F * XPAD) * sizeof(float);
    cudaFuncSetAttribute(k_gemm, cudaFuncAttributeMaxDynamicSharedMemorySize, (int)shm);

    // graph preprocessing (runs every replay)
    k_detect<<<1, 256>>>(EI, BT);
    k_init_deg<<<(NNODES + 255) / 256, 256>>>();
    k_hist<<<(NEDGES + 255) / 256, 256>>>(EI);
    k_scan1<<<NSB, SCAN_B>>>();
    k_scan2<<<1, 32>>>();
    k_scan3<<<NSB, SCAN_B>>>();
    k_fill<<<(ETOT + 255) / 256, 256>>>(EI);

    int gemm_grid = (NNODES + NB - 1) / NB;
    int agg_grid = (NNODES * 32 + 255) / 256;

    k_gemm<<<gemm_grid, 256, shm>>>(X, W1, b1, H);
    k_agg<<<agg_grid, 256>>>(H, Xb);
    k_gemm<<<gemm_grid, 256, shm>>>(Xb, W2, b2, H);
    k_agg<<<agg_grid, 256>>>(H, Xb);
    k_gemm<<<gemm_grid, 256, shm>>>(Xb, W3, b3, H);
    k_agg<<<agg_grid, 256>>>(H, Xb);

    k_pool<<<NG, F>>>(BT);
    k_mlp<<<NG, F>>>(Wm1, bm1, Wm2, bm2, out);
}

// round 5
// speedup vs baseline: 1.4772x; 1.2016x over previous
#include <cuda_runtime.h>
#include <math.h>

#define NNODES 100000
#define NEDGES 1600000
#define ETOT   (NEDGES + NNODES)
#define F      128
#define NG     128
#define NC     10
#define SCAN_B 1024
#define NSB    ((NNODES + SCAN_B - 1) / SCAN_B)
#define NB     64      // nodes per GEMM block
#define XPAD   66      // transposed-x row pad (8B alignment + reduced conflicts)

// ---------------- scratch (device globals; no allocation allowed) -------------
__device__ __align__(256) int   g_deg[NNODES];
__device__ __align__(256) int   g_off[NNODES + 1];
__device__ __align__(256) int   g_cur[NNODES];
__device__ __align__(256) float g_dis[NNODES];
__device__ __align__(256) int   g_ccol[ETOT];
__device__ __align__(256) float g_cnrm[ETOT];
__device__ __align__(256) float g_h[(size_t)NNODES * F];
__device__ __align__(256) float g_x[(size_t)NNODES * F];
__device__ __align__(256) float g_pool[NG * 2 * F];
__device__ int g_bs[NSB];
__device__ int g_flags[2];

// ---------------- stream/events for fork-join overlap (created pre-main) -----
static cudaStream_t s2;
static cudaEvent_t evFork, evJoin;
struct StreamInit {
    StreamInit() {
        cudaStreamCreateWithFlags(&s2, cudaStreamNonBlocking);
        cudaEventCreateWithFlags(&evFork, cudaEventDisableTiming);
        cudaEventCreateWithFlags(&evJoin, cudaEventDisableTiming);
    }
};
static StreamInit s_init;

// ---------------- f32x2 helpers (packed fp32: 2x FFMA rate) ------------------
__device__ __forceinline__ unsigned long long pack2(float x) {
    unsigned long long r;
    asm("mov.b64 %0, {%1, %1};" : "=l"(r) : "f"(x));
    return r;
}
__device__ __forceinline__ void ffma2(unsigned long long& d, unsigned long long a,
                                      unsigned long long b) {
    asm("fma.rn.f32x2 %0, %1, %2, %0;" : "+l"(d) : "l"(a), "l"(b));
}
__device__ __forceinline__ float lo32(unsigned long long v) { return __uint_as_float((unsigned)v); }
__device__ __forceinline__ float hi32(unsigned long long v) { return __uint_as_float((unsigned)(v >> 32)); }

// ---------------- helpers ----------------------------------------------------
__device__ __forceinline__ int load_idx(const void* p, long long i, int is64) {
    return is64 ? (int)(((const long long*)p)[i]) : ((const int*)p)[i];
}

// dtype detection (jax x64 ambiguity); see round-1 notes.
__global__ void k_detect(const void* ei, const void* batch) {
    __shared__ int s_bad;
    if (threadIdx.x == 0) s_bad = 0;
    __syncthreads();
    const int* b32 = (const int*)batch;
    int bad = 0;
    for (int j = threadIdx.x; j < NNODES - 1; j += blockDim.x) {
        int a = b32[j], c = b32[j + 1];
        if (a < 0 || a >= NG || c < a) { bad = 1; break; }
    }
    if (bad) atomicExch(&s_bad, 1);
    __syncthreads();
    if (threadIdx.x == 0) {
        g_flags[1] = s_bad ? 1 : 0;
        const long long* p = (const long long*)ei;
        int ok = 1;
        for (int i = 0; i < 64; i++) {
            long long v = p[(long long)i * 317 + 1];
            if (v < 0 || v >= NNODES) { ok = 0; break; }
        }
        g_flags[0] = ok;
    }
}

__global__ void k_init_deg() {
    int i = blockIdx.x * blockDim.x + threadIdx.x;
    if (i < NNODES) g_deg[i] = 1;
}

__global__ void k_hist(const void* ei) {
    int is64 = g_flags[0];
    int i = blockIdx.x * blockDim.x + threadIdx.x;
    if (i < NEDGES) {
        int r = load_idx(ei, i, is64);
        atomicAdd(&g_deg[r], 1);
    }
}

__global__ void k_scan1() {
    __shared__ int s[SCAN_B];
    int i = blockIdx.x * SCAN_B + threadIdx.x;
    int v = (i < NNODES) ? g_deg[i] : 0;
    s[threadIdx.x] = v;
    __syncthreads();
    for (int d = SCAN_B / 2; d > 0; d >>= 1) {
        if (threadIdx.x < d) s[threadIdx.x] += s[threadIdx.x + d];
        __syncthreads();
    }
    if (threadIdx.x == 0) g_bs[blockIdx.x] = s[0];
}

__global__ void k_scan2() {
    if (threadIdx.x == 0 && blockIdx.x == 0) {
        int run = 0;
        for (int b = 0; b < NSB; b++) { int t = g_bs[b]; g_bs[b] = run; run += t; }
        g_off[NNODES] = run;
    }
}

__global__ void k_scan3() {
    __shared__ int s[SCAN_B];
    int tid = threadIdx.x;
    int i = blockIdx.x * SCAN_B + tid;
    int v = (i < NNODES) ? g_deg[i] : 0;
    s[tid] = v;
    __syncthreads();
    for (int d = 1; d < SCAN_B; d <<= 1) {
        int t = (tid >= d) ? s[tid - d] : 0;
        __syncthreads();
        s[tid] += t;
        __syncthreads();
    }
    if (i < NNODES) {
        int excl = s[tid] - v + g_bs[blockIdx.x];
        g_off[i] = excl;
        g_cur[i] = excl;
        g_dis[i] = rsqrtf((float)v + 1e-12f);
    }
}

__global__ void k_fill(const void* ei) {
    int is64 = g_flags[0];
    int i = blockIdx.x * blockDim.x + threadIdx.x;
    if (i < NEDGES) {
        int r = load_idx(ei, i, is64);
        int c = load_idx(ei, (long long)NEDGES + i, is64);
        int p = atomicAdd(&g_cur[r], 1);
        g_ccol[p] = c;
        g_cnrm[p] = g_dis[r] * g_dis[c];
    } else if (i < ETOT) {
        int nidx = i - NEDGES;
        int p = atomicAdd(&g_cur[nidx], 1);
        g_ccol[p] = nidx;
        float d = g_dis[nidx];
        g_cnrm[p] = d * d;
    }
}

// ---------------- GEMM with packed f32x2 FFMA (unchanged from R4) ------------
__global__ __launch_bounds__(256, 2)
void k_gemm(const float* __restrict__ in, const float* __restrict__ W,
            const float* __restrict__ b, float* __restrict__ out) {
    extern __shared__ float sm[];
    float* Ws = sm;                 // 128 x 128
    float* xs = sm + F * F;         // 128 x XPAD (transposed: xs[k*XPAD + n])

    const float4* W4 = (const float4*)W;
    float4* Ws4 = (float4*)Ws;
    for (int i = threadIdx.x; i < F * F / 4; i += 256) Ws4[i] = W4[i];

    int node0 = blockIdx.x * NB;
    const float4* in4 = (const float4*)in;
    for (int i = threadIdx.x; i < NB * 32; i += 256) {
        int n = i >> 5, kg = i & 31;
        int node = node0 + n;
        float4 v = (node < NNODES) ? in4[(size_t)node * 32 + kg]
                                   : make_float4(0.f, 0.f, 0.f, 0.f);
        xs[(4 * kg + 0) * XPAD + n] = v.x;
        xs[(4 * kg + 1) * XPAD + n] = v.y;
        xs[(4 * kg + 2) * XPAD + n] = v.z;
        xs[(4 * kg + 3) * XPAD + n] = v.w;
    }
    __syncthreads();

    int warp = threadIdx.x >> 5, lane = threadIdx.x & 31;
    int nb = warp * 8;

    unsigned long long bb[4];
#pragma unroll
    for (int d = 0; d < 4; d++) bb[d] = pack2(b[4 * lane + d]);

    unsigned long long acc[4][4];
#pragma unroll
    for (int p = 0; p < 4; p++)
#pragma unroll
        for (int d = 0; d < 4; d++) acc[p][d] = bb[d];

#pragma unroll 4
    for (int j = 0; j < 32; j++) {
        float4 w0 = Ws4[(4 * j + 0) * 32 + lane];
        float4 w1 = Ws4[(4 * j + 1) * 32 + lane];
        float4 w2 = Ws4[(4 * j + 2) * 32 + lane];
        float4 w3 = Ws4[(4 * j + 3) * 32 + lane];
        unsigned long long wd[4][4];
        wd[0][0] = pack2(w0.x); wd[0][1] = pack2(w0.y); wd[0][2] = pack2(w0.z); wd[0][3] = pack2(w0.w);
        wd[1][0] = pack2(w1.x); wd[1][1] = pack2(w1.y); wd[1][2] = pack2(w1.z); wd[1][3] = pack2(w1.w);
        wd[2][0] = pack2(w2.x); wd[2][1] = pack2(w2.y); wd[2][2] = pack2(w2.z); wd[2][3] = pack2(w2.w);
        wd[3][0] = pack2(w3.x); wd[3][1] = pack2(w3.y); wd[3][2] = pack2(w3.z); wd[3][3] = pack2(w3.w);
#pragma unroll
        for (int p = 0; p < 4; p++) {
            int nidx = nb + 2 * p;
#pragma unroll
            for (int kk = 0; kk < 4; kk++) {
                unsigned long long a =
                    *(const unsigned long long*)&xs[(4 * j + kk) * XPAD + nidx];
                ffma2(acc[p][0], a, wd[kk][0]);
                ffma2(acc[p][1], a, wd[kk][1]);
                ffma2(acc[p][2], a, wd[kk][2]);
                ffma2(acc[p][3], a, wd[kk][3]);
            }
        }
    }

    float4* out4 = (float4*)out;
#pragma unroll
    for (int p = 0; p < 4; p++) {
        int n0 = node0 + nb + 2 * p;
        int n1 = n0 + 1;
        float4 lo = make_float4(lo32(acc[p][0]), lo32(acc[p][1]), lo32(acc[p][2]), lo32(acc[p][3]));
        float4 hi = make_float4(hi32(acc[p][0]), hi32(acc[p][1]), hi32(acc[p][2]), hi32(acc[p][3]));
        if (n0 < NNODES) out4[(size_t)n0 * 32 + lane] = lo;
        if (n1 < NNODES) out4[(size_t)n1 * 32 + lane] = hi;
    }
}

// ---------------- aggregation: warp per node; 8-deep gather, 2 accumulators --
__global__ void k_agg(const float* __restrict__ h, float* __restrict__ xo) {
    int gw = (blockIdx.x * blockDim.x + threadIdx.x) >> 5;
    int lane = threadIdx.x & 31;
    if (gw >= NNODES) return;
    int beg = g_off[gw], end = g_off[gw + 1];
    const float4* h4 = (const float4*)h;
    float4 accA = make_float4(0.f, 0.f, 0.f, 0.f);
    float4 accB = make_float4(0.f, 0.f, 0.f, 0.f);
    int e = beg;
    for (; e + 8 <= end; e += 8) {
        int   c[8];
        float m[8];
#pragma unroll
        for (int u = 0; u < 8; u++) { c[u] = g_ccol[e + u]; m[u] = g_cnrm[e + u]; }
        float4 v[8];
#pragma unroll
        for (int u = 0; u < 8; u++) v[u] = h4[(size_t)c[u] * 32 + lane];
#pragma unroll
        for (int u = 0; u < 8; u += 2) {
            accA.x = fmaf(m[u], v[u].x, accA.x);
            accA.y = fmaf(m[u], v[u].y, accA.y);
            accA.z = fmaf(m[u], v[u].z, accA.z);
            accA.w = fmaf(m[u], v[u].w, accA.w);
            accB.x = fmaf(m[u + 1], v[u + 1].x, accB.x);
            accB.y = fmaf(m[u + 1], v[u + 1].y, accB.y);
            accB.z = fmaf(m[u + 1], v[u + 1].z, accB.z);
            accB.w = fmaf(m[u + 1], v[u + 1].w, accB.w);
        }
    }
    for (; e < end; e++) {
        int cc = g_ccol[e];
        float nrm = g_cnrm[e];
        float4 v = h4[(size_t)cc * 32 + lane];
        accA.x = fmaf(nrm, v.x, accA.x);
        accA.y = fmaf(nrm, v.y, accA.y);
        accA.z = fmaf(nrm, v.z, accA.z);
        accA.w = fmaf(nrm, v.w, accA.w);
    }
    float4 acc;
    acc.x = fmaxf(accA.x + accB.x, 0.f);
    acc.y = fmaxf(accA.y + accB.y, 0.f);
    acc.z = fmaxf(accA.z + accB.z, 0.f);
    acc.w = fmaxf(accA.w + accB.w, 0.f);
    ((float4*)xo)[(size_t)gw * 32 + lane] = acc;
}

// ---------------- pooling ----------------------------------------------------
__device__ __forceinline__ int lbound(const void* b, int is64, long long key) {
    int lo = 0, hi = NNODES;
    while (lo < hi) {
        int mid = (lo + hi) >> 1;
        long long v = is64 ? ((const long long*)b)[mid] : (long long)((const int*)b)[mid];
        if (v < key) lo = mid + 1; else hi = mid;
    }
    return lo;
}

__global__ void k_pool(const void* batch) {
    int g = blockIdx.x, tid = threadIdx.x;
    int is64 = g_flags[1];
    int s = lbound(batch, is64, g);
    int e = lbound(batch, is64, g + 1);
    float sum = 0.f, mx = -3.4e38f;
    int n = s;
    for (; n + 2 <= e; n += 2) {
        float v0 = g_x[(size_t)n * F + tid];
        float v1 = g_x[(size_t)(n + 1) * F + tid];
        sum += v0 + v1;
        mx = fmaxf(mx, fmaxf(v0, v1));
    }
    for (; n < e; n++) {
        float v = g_x[(size_t)n * F + tid];
        sum += v;
        mx = fmaxf(mx, v);
    }
    int cnt = e - s;
    float mean = sum / ((float)cnt + 1e-12f);
    if (cnt == 0) mx = 0.f;
    g_pool[g * 2 * F + tid] = mean;
    g_pool[g * 2 * F + F + tid] = mx;
}

// ---------------- MLP head ----------------------------------------------------
__global__ void k_mlp(const float* __restrict__ Wm1, const float* __restrict__ bm1,
                      const float* __restrict__ Wm2, const float* __restrict__ bm2,
                      float* __restrict__ out) {
    __shared__ float gs[2 * F];
    __shared__ float hs[F];
    int g = blockIdx.x, tid = threadIdx.x;
    gs[tid] = g_pool[g * 2 * F + tid];
    gs[F + tid] = g_pool[g * 2 * F + F + tid];
    __syncthreads();
    float acc = bm1[tid];
#pragma unroll 8
    for (int k = 0; k < 2 * F; k++) acc = fmaf(gs[k], Wm1[k * F + tid], acc);
    hs[tid] = fmaxf(acc, 0.f);
    __syncthreads();
    if (tid < NC) {
        float a = bm2[tid];
#pragma unroll 8
        for (int k = 0; k < F; k++) a = fmaf(hs[k], Wm2[k * NC + tid], a);
        out[g * NC + tid] = a;
    }
}

// ---------------- launch ------------------------------------------------------
extern "C" void kernel_launch(void* const* d_in, const int* in_sizes, int n_in,
                              void* d_out, int out_size) {
    int iX = -1, iEI = -1, iB = -1, iW[3] = {-1, -1, -1}, ibv[4] = {-1, -1, -1, -1};
    int nw = 0, nb = 0, iWm1 = -1, iWm2 = -1, ibm2 = -1;
    for (int i = 0; i < n_in; i++) {
        int s = in_sizes[i];
        if (s == NNODES * F) iX = i;
        else if (s == 2 * NEDGES) iEI = i;
        else if (s == NNODES) iB = i;
        else if (s == F * F) { if (nw < 3) iW[nw++] = i; }
        else if (s == F) { if (nb < 4) ibv[nb++] = i; }
        else if (s == 2 * F * F) iWm1 = i;
        else if (s == F * NC) iWm2 = i;
        else if (s == NC) ibm2 = i;
    }
    const float* X   = (const float*)d_in[iX];
    const void*  EI  = d_in[iEI];
    const void*  BT  = d_in[iB];
    const float* W1  = (const float*)d_in[iW[0]];
    const float* W2  = (const float*)d_in[iW[1]];
    const float* W3  = (const float*)d_in[iW[2]];
    const float* b1  = (const float*)d_in[ibv[0]];
    const float* b2  = (const float*)d_in[ibv[1]];
    const float* b3  = (const float*)d_in[ibv[2]];
    const float* bm1 = (const float*)d_in[ibv[3]];
    const float* Wm1 = (const float*)d_in[iWm1];
    const float* Wm2 = (const float*)d_in[iWm2];
    const float* bm2 = (const float*)d_in[ibm2];
    float* out = (float*)d_out;

    void *ph = nullptr, *px = nullptr;
    cudaGetSymbolAddress(&ph, g_h);
    cudaGetSymbolAddress(&px, g_x);
    float* H = (float*)ph;
    float* Xb = (float*)px;

    size_t shm = (size_t)(F * F + F * XPAD) * sizeof(float);
    cudaFuncSetAttribute(k_gemm, cudaFuncAttributeMaxDynamicSharedMemorySize, (int)shm);

    int gemm_grid = (NNODES + NB - 1) / NB;
    int agg_grid = (NNODES * 32 + 255) / 256;

    // Fork: layer-1 GEMM (depends only on X/W1) runs on s2, concurrent with
    // the CSR build on the main stream. Join before the first aggregation.
    cudaEventRecord(evFork, 0);
    cudaStreamWaitEvent(s2, evFork, 0);
    k_gemm<<<gemm_grid, 256, shm, s2>>>(X, W1, b1, H);
    cudaEventRecord(evJoin, s2);

    // CSR preprocessing on the main stream
    k_detect<<<1, 1024>>>(EI, BT);
    k_init_deg<<<(NNODES + 255) / 256, 256>>>();
    k_hist<<<(NEDGES + 255) / 256, 256>>>(EI);
    k_scan1<<<NSB, SCAN_B>>>();
    k_scan2<<<1, 32>>>();
    k_scan3<<<NSB, SCAN_B>>>();
    k_fill<<<(ETOT + 255) / 256, 256>>>(EI);

    cudaStreamWaitEvent(0, evJoin, 0);

    k_agg<<<agg_grid, 256>>>(H, Xb);
    k_gemm<<<gemm_grid, 256, shm>>>(Xb, W2, b2, H);
    k_agg<<<agg_grid, 256>>>(H, Xb);
    k_gemm<<<gemm_grid, 256, shm>>>(Xb, W3, b3, H);
    k_agg<<<agg_grid, 256>>>(H, Xb);

    k_pool<<<NG, F>>>(BT);
    k_mlp<<<NG, F>>>(Wm1, bm1, Wm2, bm2, out);
}